// round 1
// baseline (speedup 1.0000x reference)
#include <cuda_runtime.h>
#include <math.h>

// ---------------------------------------------------------------------------
// iTransformer encoder, fp32 baseline.
// B=16, S=1024, T=512, D=256, H=8, DH=32, L=4, FF=1024. M = B*S = 16384 rows.
// ---------------------------------------------------------------------------

#define M_ROWS 16384
#define D_MODEL 256
#define T_IN 512
#define FF_DIM 1024
#define N_HEADS 8
#define DH 32
#define SEQ 1024
#define N_LAYERS 4

// Scratch (device globals: allocation-free contract)
__device__ float g_y[M_ROWS * D_MODEL];      // normed activations
__device__ float g_h[M_ROWS * D_MODEL];      // residual stream
__device__ float g_qkv[M_ROWS * 3 * D_MODEL];
__device__ float g_att[M_ROWS * D_MODEL];
__device__ float g_ff[M_ROWS * FF_DIM];

// ---------------------------------------------------------------------------
// GEMM: C[M,N] = A[M,K] @ B[N,K]^T + bias[N]  (+ReLU) (+residual)
// BM=128, BN=64, BK=16, 256 threads, 8x4 per thread.
// M % 128 == 0, N % 64 == 0, K % 16 == 0 (all shapes here satisfy this).
// ---------------------------------------------------------------------------
template <bool RELU, bool RES>
__global__ __launch_bounds__(256, 2) void gemm_kernel(
    const float* __restrict__ A, const float* __restrict__ B,
    const float* __restrict__ bias, const float* __restrict__ res,
    float* __restrict__ C, int M, int N, int K) {
  __shared__ float As[16][132];  // padded: conflict-free transposed stores
  __shared__ float Bs[16][68];

  const int tid = threadIdx.x;
  const int tx = tid & 15;        // 0..15 -> 4 cols each
  const int ty = tid >> 4;        // 0..15 -> 8 rows each
  const int m0 = blockIdx.y * 128;
  const int n0 = blockIdx.x * 64;

  const int lrow = tid >> 2;          // 0..63
  const int lcol = (tid & 3) << 2;    // 0,4,8,12

  const float* Aptr  = A + (size_t)(m0 + lrow) * K + lcol;
  const float* Aptr2 = Aptr + (size_t)64 * K;
  const float* Bptr  = B + (size_t)(n0 + lrow) * K + lcol;

  float acc[8][4];
#pragma unroll
  for (int i = 0; i < 8; i++)
#pragma unroll
    for (int j = 0; j < 4; j++) acc[i][j] = 0.f;

  for (int k0 = 0; k0 < K; k0 += 16) {
    float4 a0 = *(const float4*)(Aptr + k0);
    float4 a1 = *(const float4*)(Aptr2 + k0);
    float4 b0 = *(const float4*)(Bptr + k0);
    __syncthreads();
    As[lcol + 0][lrow] = a0.x; As[lcol + 1][lrow] = a0.y;
    As[lcol + 2][lrow] = a0.z; As[lcol + 3][lrow] = a0.w;
    As[lcol + 0][lrow + 64] = a1.x; As[lcol + 1][lrow + 64] = a1.y;
    As[lcol + 2][lrow + 64] = a1.z; As[lcol + 3][lrow + 64] = a1.w;
    Bs[lcol + 0][lrow] = b0.x; Bs[lcol + 1][lrow] = b0.y;
    Bs[lcol + 2][lrow] = b0.z; Bs[lcol + 3][lrow] = b0.w;
    __syncthreads();
#pragma unroll
    for (int kk = 0; kk < 16; kk++) {
      float4 av0 = *(const float4*)&As[kk][ty * 8];
      float4 av1 = *(const float4*)&As[kk][ty * 8 + 4];
      float4 bv  = *(const float4*)&Bs[kk][tx * 4];
      float a[8] = {av0.x, av0.y, av0.z, av0.w, av1.x, av1.y, av1.z, av1.w};
      float b[4] = {bv.x, bv.y, bv.z, bv.w};
#pragma unroll
      for (int i = 0; i < 8; i++)
#pragma unroll
        for (int j = 0; j < 4; j++) acc[i][j] = fmaf(a[i], b[j], acc[i][j]);
    }
  }

  const int col = n0 + tx * 4;
  float4 bb = *(const float4*)&bias[col];
#pragma unroll
  for (int i = 0; i < 8; i++) {
    int row = m0 + ty * 8 + i;
    float4 r;
    r.x = acc[i][0] + bb.x;
    r.y = acc[i][1] + bb.y;
    r.z = acc[i][2] + bb.z;
    r.w = acc[i][3] + bb.w;
    if (RELU) {
      r.x = fmaxf(r.x, 0.f); r.y = fmaxf(r.y, 0.f);
      r.z = fmaxf(r.z, 0.f); r.w = fmaxf(r.w, 0.f);
    }
    if (RES) {
      float4 rr = *(const float4*)&res[(size_t)row * N + col];
      r.x += rr.x; r.y += rr.y; r.z += rr.z; r.w += rr.w;
    }
    *(float4*)&C[(size_t)row * N + col] = r;
  }
}

// ---------------------------------------------------------------------------
// LayerNorm over last dim (256). One block per row, 256 threads.
// ---------------------------------------------------------------------------
__global__ __launch_bounds__(256) void ln_kernel(
    const float* __restrict__ in, const float* __restrict__ g,
    const float* __restrict__ b, float* __restrict__ out) {
  const int row = blockIdx.x;
  const int t = threadIdx.x;
  float v = in[(size_t)row * D_MODEL + t];

  float s = v;
#pragma unroll
  for (int o = 16; o > 0; o >>= 1) s += __shfl_xor_sync(0xffffffffu, s, o);
  __shared__ float ws[8];
  __shared__ float ws2[8];
  if ((t & 31) == 0) ws[t >> 5] = s;
  __syncthreads();
  float mean = (ws[0] + ws[1] + ws[2] + ws[3] + ws[4] + ws[5] + ws[6] + ws[7]) *
               (1.0f / 256.0f);
  float d = v - mean;
  float s2 = d * d;
#pragma unroll
  for (int o = 16; o > 0; o >>= 1) s2 += __shfl_xor_sync(0xffffffffu, s2, o);
  if ((t & 31) == 0) ws2[t >> 5] = s2;
  __syncthreads();
  float var = (ws2[0] + ws2[1] + ws2[2] + ws2[3] + ws2[4] + ws2[5] + ws2[6] +
               ws2[7]) * (1.0f / 256.0f);
  out[(size_t)row * D_MODEL + t] = d * rsqrtf(var + 1e-5f) * g[t] + b[t];
}

// ---------------------------------------------------------------------------
// RoPE in-place on q,k slices of qkv. One thread per (row, head, freq-pair).
// ---------------------------------------------------------------------------
__global__ __launch_bounds__(256) void rope_kernel(float* __restrict__ qkv) {
  int idx = blockIdx.x * 256 + threadIdx.x;  // M_ROWS * 8 * 16
  int j = idx & 15;
  int h = (idx >> 4) & 7;
  int row = idx >> 7;
  int s = row & (SEQ - 1);
  // inv_freq = 10000^{-j/16} = 2^{-j*log2(10000)/16}
  float freq = (float)s * exp2f(-0.8304820237218406f * (float)j);
  float c, sn;
  sincosf(freq, &c, &sn);
  size_t base = (size_t)row * 768 + h * 32 + j;
  float q1 = qkv[base], q2 = qkv[base + 16];
  qkv[base]      = q1 * c - q2 * sn;
  qkv[base + 16] = q2 * c + q1 * sn;
  float k1 = qkv[base + 256], k2 = qkv[base + 272];
  qkv[base + 256] = k1 * c - k2 * sn;
  qkv[base + 272] = k2 * c + k1 * sn;
}

// ---------------------------------------------------------------------------
// Flash-style attention. Grid: (S/64, B*H). Block: 256 threads.
// Each block: 64 query rows x full DH=32, online softmax over 16 K-tiles of 64.
// ---------------------------------------------------------------------------
#define BQ 64
#define BKT 64
__global__ __launch_bounds__(256) void attn_kernel(
    const float* __restrict__ qkv, float* __restrict__ out) {
  __shared__ float Qt[DH][BQ];       // d-major, pre-scaled
  __shared__ float Kt[DH][BKT];      // d-major
  __shared__ float Vs[BKT][DH];
  __shared__ float Ss[BQ][BKT + 1];  // scores -> probs
  __shared__ float m_row[BQ], l_row[BQ], cfs[BQ];
  __shared__ float pmax[4][BQ], psum[4][BQ];

  const int tid = threadIdx.x;
  const int bh = blockIdx.y;
  const int b = bh >> 3;
  const int h = bh & 7;
  const int q0 = blockIdx.x * BQ;
  const float scale = 0.17677669529663687f;  // 1/sqrt(32)

  const int r = tid >> 2;           // 0..63
  const int dc = (tid & 3) << 3;    // 0,8,16,24

  // Load Q tile (scaled), transposed to d-major
  {
    const float* qb = qkv + (size_t)(b * SEQ + q0 + r) * 768 + h * 32 + dc;
#pragma unroll
    for (int i = 0; i < 8; i++) Qt[dc + i][r] = qb[i] * scale;
  }
  if (tid < BQ) { m_row[tid] = -INFINITY; l_row[tid] = 0.f; }

  float O[8];
#pragma unroll
  for (int i = 0; i < 8; i++) O[i] = 0.f;

  const int tx = tid & 15;   // score cols: tx*4..+3
  const int ty = tid >> 4;   // score rows: ty*4..+3
  const int sr = tid & 63;   // softmax row
  const int sl = tid >> 6;   // softmax col slice (16 cols)

  for (int kt = 0; kt < SEQ / BKT; kt++) {
    const int k0 = kt * BKT;
    __syncthreads();  // protect Kt/Vs/Ss from previous iteration readers
    {
      const float* kb = qkv + (size_t)(b * SEQ + k0 + r) * 768 + 256 + h * 32 + dc;
      const float* vb = kb + 256;
#pragma unroll
      for (int i = 0; i < 8; i++) Kt[dc + i][r] = kb[i];
#pragma unroll
      for (int i = 0; i < 8; i++) Vs[r][dc + i] = vb[i];
    }
    __syncthreads();

    // Scores: 4x4 per thread
    float s4[4][4];
#pragma unroll
    for (int i = 0; i < 4; i++)
#pragma unroll
      for (int j = 0; j < 4; j++) s4[i][j] = 0.f;
#pragma unroll
    for (int d = 0; d < DH; d++) {
      float4 qv = *(const float4*)&Qt[d][ty * 4];
      float4 kv = *(const float4*)&Kt[d][tx * 4];
      float qa[4] = {qv.x, qv.y, qv.z, qv.w};
      float ka[4] = {kv.x, kv.y, kv.z, kv.w};
#pragma unroll
      for (int i = 0; i < 4; i++)
#pragma unroll
        for (int j = 0; j < 4; j++) s4[i][j] = fmaf(qa[i], ka[j], s4[i][j]);
    }
#pragma unroll
    for (int i = 0; i < 4; i++)
#pragma unroll
      for (int j = 0; j < 4; j++) Ss[ty * 4 + i][tx * 4 + j] = s4[i][j];
    __syncthreads();

    // Softmax pass 1: partial max
    float lm = -INFINITY;
#pragma unroll
    for (int c = 0; c < 16; c++) lm = fmaxf(lm, Ss[sr][sl * 16 + c]);
    pmax[sl][sr] = lm;
    __syncthreads();
    if (tid < BQ) {
      float mo = m_row[tid];
      float mn = fmaxf(fmaxf(pmax[0][tid], pmax[1][tid]),
                       fmaxf(pmax[2][tid], pmax[3][tid]));
      mn = fmaxf(mo, mn);
      cfs[tid] = __expf(mo - mn);  // exp(-inf)=0 first tile
      m_row[tid] = mn;
    }
    __syncthreads();

    // Softmax pass 2: exponentiate + partial sums
    float mr = m_row[sr];
    float ps = 0.f;
#pragma unroll
    for (int c = 0; c < 16; c++) {
      float p = __expf(Ss[sr][sl * 16 + c] - mr);
      Ss[sr][sl * 16 + c] = p;
      ps += p;
    }
    psum[sl][sr] = ps;
    __syncthreads();
    if (tid < BQ) {
      l_row[tid] = l_row[tid] * cfs[tid] +
                   psum[0][tid] + psum[1][tid] + psum[2][tid] + psum[3][tid];
    }

    // Accumulate O (each thread: row r, dims dc..dc+7)
    float cf = cfs[r];
#pragma unroll
    for (int i = 0; i < 8; i++) O[i] *= cf;
    for (int j = 0; j < BKT; j++) {
      float p = Ss[r][j];
      float4 v0 = *(const float4*)&Vs[j][dc];
      float4 v1 = *(const float4*)&Vs[j][dc + 4];
      O[0] = fmaf(p, v0.x, O[0]); O[1] = fmaf(p, v0.y, O[1]);
      O[2] = fmaf(p, v0.z, O[2]); O[3] = fmaf(p, v0.w, O[3]);
      O[4] = fmaf(p, v1.x, O[4]); O[5] = fmaf(p, v1.y, O[5]);
      O[6] = fmaf(p, v1.z, O[6]); O[7] = fmaf(p, v1.w, O[7]);
    }
  }
  __syncthreads();
  float inv = 1.0f / l_row[r];
  float* ob = out + (size_t)(b * SEQ + q0 + r) * D_MODEL + h * 32 + dc;
#pragma unroll
  for (int i = 0; i < 8; i++) ob[i] = O[i] * inv;
}

// ---------------------------------------------------------------------------
// Launch
// ---------------------------------------------------------------------------
extern "C" void kernel_launch(void* const* d_in, const int* in_sizes, int n_in,
                              void* d_out, int out_size) {
  const float* x         = (const float*)d_in[0];
  const float* tok_w     = (const float*)d_in[1];
  const float* tok_b     = (const float*)d_in[2];
  const float* tnorm_g   = (const float*)d_in[3];
  const float* tnorm_b   = (const float*)d_in[4];
  const float* in_proj_w = (const float*)d_in[5];
  const float* in_proj_b = (const float*)d_in[6];
  const float* out_w     = (const float*)d_in[7];
  const float* out_b     = (const float*)d_in[8];
  const float* ln1_g     = (const float*)d_in[9];
  const float* ln1_b     = (const float*)d_in[10];
  const float* ln2_g     = (const float*)d_in[11];
  const float* ln2_b     = (const float*)d_in[12];
  const float* lin1_w    = (const float*)d_in[13];
  const float* lin1_b    = (const float*)d_in[14];
  const float* lin2_w    = (const float*)d_in[15];
  const float* lin2_b    = (const float*)d_in[16];
  const float* fnorm_g   = (const float*)d_in[17];
  const float* fnorm_b   = (const float*)d_in[18];
  float* out = (float*)d_out;

  float *y, *h, *qkv, *att, *ff;
  cudaGetSymbolAddress((void**)&y, g_y);
  cudaGetSymbolAddress((void**)&h, g_h);
  cudaGetSymbolAddress((void**)&qkv, g_qkv);
  cudaGetSymbolAddress((void**)&att, g_att);
  cudaGetSymbolAddress((void**)&ff, g_ff);

  const int M = M_ROWS;
  dim3 blk(256);

  // Tokenize: y = x @ tok_w^T + tok_b ; h = LN(y)
  gemm_kernel<false, false><<<dim3(D_MODEL / 64, M / 128), blk>>>(
      x, tok_w, tok_b, nullptr, y, M, D_MODEL, T_IN);
  ln_kernel<<<M, blk>>>(y, tnorm_g, tnorm_b, h);

  for (int i = 0; i < N_LAYERS; i++) {
    // Attention block
    ln_kernel<<<M, blk>>>(h, ln1_g + i * D_MODEL, ln1_b + i * D_MODEL, y);
    gemm_kernel<false, false><<<dim3(768 / 64, M / 128), blk>>>(
        y, in_proj_w + (size_t)i * 768 * D_MODEL, in_proj_b + i * 768, nullptr,
        qkv, M, 768, D_MODEL);
    rope_kernel<<<(M_ROWS * 128) / 256, blk>>>(qkv);
    attn_kernel<<<dim3(SEQ / BQ, 16 * N_HEADS), blk>>>(qkv, att);
    gemm_kernel<false, true><<<dim3(D_MODEL / 64, M / 128), blk>>>(
        att, out_w + (size_t)i * D_MODEL * D_MODEL, out_b + i * D_MODEL, h, h,
        M, D_MODEL, D_MODEL);
    // FFN block
    ln_kernel<<<M, blk>>>(h, ln2_g + i * D_MODEL, ln2_b + i * D_MODEL, y);
    gemm_kernel<true, false><<<dim3(FF_DIM / 64, M / 128), blk>>>(
        y, lin1_w + (size_t)i * FF_DIM * D_MODEL, lin1_b + i * FF_DIM, nullptr,
        ff, M, FF_DIM, D_MODEL);
    gemm_kernel<false, true><<<dim3(D_MODEL / 64, M / 128), blk>>>(
        ff, lin2_w + (size_t)i * D_MODEL * FF_DIM, lin2_b + i * D_MODEL, h, h,
        M, D_MODEL, FF_DIM);
  }

  ln_kernel<<<M, blk>>>(h, fnorm_g, fnorm_b, out);
}

// round 2
// speedup vs baseline: 1.0771x; 1.0771x over previous
#include <cuda_runtime.h>
#include <math.h>

// ---------------------------------------------------------------------------
// iTransformer encoder, fp32, round 2: 128x128x8 double-buffered SGEMM +
// register-softmax flash attention + precise RoPE.
// B=16, S=1024, T=512, D=256, H=8, DH=32, L=4, FF=1024. M = B*S = 16384.
// ---------------------------------------------------------------------------

#define M_ROWS 16384
#define D_MODEL 256
#define T_IN 512
#define FF_DIM 1024
#define N_HEADS 8
#define DH 32
#define SEQ 1024
#define N_LAYERS 4

__device__ float g_y[M_ROWS * D_MODEL];
__device__ float g_h[M_ROWS * D_MODEL];
__device__ float g_qkv[M_ROWS * 3 * D_MODEL];
__device__ float g_att[M_ROWS * D_MODEL];
__device__ float g_ff[M_ROWS * FF_DIM];

// ---------------------------------------------------------------------------
// GEMM: C[M,N] = A[M,K] @ B[N,K]^T + bias[N]  (+ReLU) (+residual)
// BM=128, BN=128, BK=8, 256 threads, 8x8 per thread, double-buffered smem.
// Requires M%128==0, N%128==0, K%16==0 (true for all call sites).
// ---------------------------------------------------------------------------
#define GEMM_COMPUTE(BUFIDX)                                                 \
  _Pragma("unroll") for (int kk = 0; kk < 8; kk++) {                         \
    float4 a0 = *(const float4*)&As[BUFIDX][kk][ty * 4];                     \
    float4 a1 = *(const float4*)&As[BUFIDX][kk][ty * 4 + 64];                \
    float4 b0 = *(const float4*)&Bs[BUFIDX][kk][tx * 4];                     \
    float4 b1 = *(const float4*)&Bs[BUFIDX][kk][tx * 4 + 64];                \
    float ra[8] = {a0.x, a0.y, a0.z, a0.w, a1.x, a1.y, a1.z, a1.w};          \
    float rb[8] = {b0.x, b0.y, b0.z, b0.w, b1.x, b1.y, b1.z, b1.w};          \
    _Pragma("unroll") for (int i = 0; i < 8; i++)                            \
        _Pragma("unroll") for (int j = 0; j < 8; j++) acc[i][j] =            \
        fmaf(ra[i], rb[j], acc[i][j]);                                       \
  }

template <bool RELU, bool RES>
__global__ __launch_bounds__(256, 2) void gemm_kernel(
    const float* __restrict__ A, const float* __restrict__ B,
    const float* __restrict__ bias, const float* __restrict__ res,
    float* __restrict__ C, int M, int N, int K) {
  __shared__ float As[2][8][132];
  __shared__ float Bs[2][8][132];

  const int tid = threadIdx.x;
  const int tx = tid & 15;
  const int ty = tid >> 4;
  const int m0 = blockIdx.y * 128;
  const int n0 = blockIdx.x * 128;

  const int lr = tid >> 1;         // 0..127
  const int lc = (tid & 1) * 4;    // 0 or 4

  const float* Ap = A + (size_t)(m0 + lr) * K + lc;
  const float* Bp = B + (size_t)(n0 + lr) * K + lc;

  float acc[8][8];
#pragma unroll
  for (int i = 0; i < 8; i++)
#pragma unroll
    for (int j = 0; j < 8; j++) acc[i][j] = 0.f;

  {
    float4 va = *(const float4*)Ap;
    float4 vb = *(const float4*)Bp;
    As[0][lc + 0][lr] = va.x; As[0][lc + 1][lr] = va.y;
    As[0][lc + 2][lr] = va.z; As[0][lc + 3][lr] = va.w;
    Bs[0][lc + 0][lr] = vb.x; Bs[0][lc + 1][lr] = vb.y;
    Bs[0][lc + 2][lr] = vb.z; Bs[0][lc + 3][lr] = vb.w;
  }
  __syncthreads();

  int buf = 0;
  for (int k0 = 8; k0 < K; k0 += 8) {
    float4 na = *(const float4*)(Ap + k0);
    float4 nb = *(const float4*)(Bp + k0);
    GEMM_COMPUTE(buf);
    int nxt = buf ^ 1;
    As[nxt][lc + 0][lr] = na.x; As[nxt][lc + 1][lr] = na.y;
    As[nxt][lc + 2][lr] = na.z; As[nxt][lc + 3][lr] = na.w;
    Bs[nxt][lc + 0][lr] = nb.x; Bs[nxt][lc + 1][lr] = nb.y;
    Bs[nxt][lc + 2][lr] = nb.z; Bs[nxt][lc + 3][lr] = nb.w;
    __syncthreads();
    buf = nxt;
  }
  GEMM_COMPUTE(buf);

#pragma unroll
  for (int jb = 0; jb < 2; jb++) {
    const int col = n0 + tx * 4 + jb * 64;
    float4 bb = *(const float4*)&bias[col];
#pragma unroll
    for (int i = 0; i < 8; i++) {
      const int row = m0 + ty * 4 + (i & 3) + (i >> 2) * 64;
      float4 r;
      r.x = acc[i][jb * 4 + 0] + bb.x;
      r.y = acc[i][jb * 4 + 1] + bb.y;
      r.z = acc[i][jb * 4 + 2] + bb.z;
      r.w = acc[i][jb * 4 + 3] + bb.w;
      if (RELU) {
        r.x = fmaxf(r.x, 0.f); r.y = fmaxf(r.y, 0.f);
        r.z = fmaxf(r.z, 0.f); r.w = fmaxf(r.w, 0.f);
      }
      if (RES) {
        float4 rr = *(const float4*)&res[(size_t)row * N + col];
        r.x += rr.x; r.y += rr.y; r.z += rr.z; r.w += rr.w;
      }
      *(float4*)&C[(size_t)row * N + col] = r;
    }
  }
}

// ---------------------------------------------------------------------------
// LayerNorm over last dim (256). One block per row.
// ---------------------------------------------------------------------------
__global__ __launch_bounds__(256) void ln_kernel(
    const float* __restrict__ in, const float* __restrict__ g,
    const float* __restrict__ b, float* __restrict__ out) {
  const int row = blockIdx.x;
  const int t = threadIdx.x;
  float v = in[(size_t)row * D_MODEL + t];

  float s = v;
#pragma unroll
  for (int o = 16; o > 0; o >>= 1) s += __shfl_xor_sync(0xffffffffu, s, o);
  __shared__ float ws[8];
  __shared__ float ws2[8];
  if ((t & 31) == 0) ws[t >> 5] = s;
  __syncthreads();
  float mean = (ws[0] + ws[1] + ws[2] + ws[3] + ws[4] + ws[5] + ws[6] + ws[7]) *
               (1.0f / 256.0f);
  float d = v - mean;
  float s2 = d * d;
#pragma unroll
  for (int o = 16; o > 0; o >>= 1) s2 += __shfl_xor_sync(0xffffffffu, s2, o);
  if ((t & 31) == 0) ws2[t >> 5] = s2;
  __syncthreads();
  float var = (ws2[0] + ws2[1] + ws2[2] + ws2[3] + ws2[4] + ws2[5] + ws2[6] +
               ws2[7]) * (1.0f / 256.0f);
  out[(size_t)row * D_MODEL + t] = d * rsqrtf(var + 1e-5f) * g[t] + b[t];
}

// ---------------------------------------------------------------------------
// RoPE in-place on q,k of qkv. Replicates reference float32 math closely:
// inv_freq = 1/powf(10000, j/16); freq = s*inv_freq; accurate sincosf.
// ---------------------------------------------------------------------------
__global__ __launch_bounds__(256) void rope_kernel(float* __restrict__ qkv) {
  int idx = blockIdx.x * 256 + threadIdx.x;  // M_ROWS * 8 * 16
  int j = idx & 15;
  int h = (idx >> 4) & 7;
  int row = idx >> 7;
  int s = row & (SEQ - 1);
  float inv_freq = 1.0f / powf(10000.0f, (float)j * 0.0625f);
  float freq = (float)s * inv_freq;
  float c, sn;
  sincosf(freq, &c, &sn);
  size_t base = (size_t)row * 768 + h * 32 + j;
  float q1 = qkv[base], q2 = qkv[base + 16];
  qkv[base]      = q1 * c - q2 * sn;
  qkv[base + 16] = q2 * c + q1 * sn;
  float k1 = qkv[base + 256], k2 = qkv[base + 272];
  qkv[base + 256] = k1 * c - k2 * sn;
  qkv[base + 272] = k2 * c + k1 * sn;
}

// ---------------------------------------------------------------------------
// Flash attention, register softmax. Grid (S/64, B*H), 256 threads.
// Score threads: ty=tid>>4 owns rows ty*4..+3, tx=tid&15 owns cols tx*4..+3.
// Row reductions via shuffles across the 16 tx lanes (offsets 1,2,4,8).
// ---------------------------------------------------------------------------
#define BQ 64
#define BKT 64
__global__ __launch_bounds__(256) void attn_kernel(
    const float* __restrict__ qkv, float* __restrict__ out) {
  __shared__ float Qt[DH][BQ];        // d-major, pre-scaled
  __shared__ float Kt[DH][BKT];       // d-major
  __shared__ float Vs[BKT][36];       // padded rows
  __shared__ float Ss[BQ][BKT + 1];   // probs
  __shared__ float cfs[BQ];
  __shared__ float lfin[BQ];

  const int tid = threadIdx.x;
  const int bh = blockIdx.y;
  const int b = bh >> 3;
  const int h = bh & 7;
  const int q0 = blockIdx.x * BQ;
  const float scale = 0.17677669529663687f;  // 1/sqrt(32)

  const int r = tid >> 2;          // 0..63 (load / AV row)
  const int dc = (tid & 3) << 3;   // 0,8,16,24

  {
    const float* qb = qkv + (size_t)(b * SEQ + q0 + r) * 768 + h * 32 + dc;
#pragma unroll
    for (int i = 0; i < 8; i++) Qt[dc + i][r] = qb[i] * scale;
  }

  const int tx = tid & 15;
  const int ty = tid >> 4;

  float m_i[4], l_i[4];
#pragma unroll
  for (int i = 0; i < 4; i++) { m_i[i] = -INFINITY; l_i[i] = 0.f; }
  float O[8];
#pragma unroll
  for (int i = 0; i < 8; i++) O[i] = 0.f;

  for (int kt = 0; kt < SEQ / BKT; kt++) {
    const int k0 = kt * BKT;
    __syncthreads();  // protect Kt/Vs/Ss from previous iteration readers
    {
      const float* kb =
          qkv + (size_t)(b * SEQ + k0 + r) * 768 + 256 + h * 32 + dc;
      const float* vb = kb + 256;
#pragma unroll
      for (int i = 0; i < 8; i++) Kt[dc + i][r] = kb[i];
#pragma unroll
      for (int i = 0; i < 8; i++) Vs[r][dc + i] = vb[i];
    }
    __syncthreads();

    // Scores 4x4 per thread
    float s4[4][4];
#pragma unroll
    for (int i = 0; i < 4; i++)
#pragma unroll
      for (int j = 0; j < 4; j++) s4[i][j] = 0.f;
#pragma unroll
    for (int d = 0; d < DH; d++) {
      float4 qv = *(const float4*)&Qt[d][ty * 4];
      float4 kv = *(const float4*)&Kt[d][tx * 4];
      float qa[4] = {qv.x, qv.y, qv.z, qv.w};
      float ka[4] = {kv.x, kv.y, kv.z, kv.w};
#pragma unroll
      for (int i = 0; i < 4; i++)
#pragma unroll
        for (int j = 0; j < 4; j++) s4[i][j] = fmaf(qa[i], ka[j], s4[i][j]);
    }

    // Register softmax: per-row reduce across 16 tx lanes via shuffles
    float cf_i[4];
#pragma unroll
    for (int i = 0; i < 4; i++) {
      float lm = fmaxf(fmaxf(s4[i][0], s4[i][1]), fmaxf(s4[i][2], s4[i][3]));
#pragma unroll
      for (int o = 8; o > 0; o >>= 1)
        lm = fmaxf(lm, __shfl_xor_sync(0xffffffffu, lm, o));
      float mn = fmaxf(m_i[i], lm);
      cf_i[i] = __expf(m_i[i] - mn);  // 0 on first tile
      m_i[i] = mn;
      float ps = 0.f;
#pragma unroll
      for (int j = 0; j < 4; j++) {
        float p = __expf(s4[i][j] - mn);
        Ss[ty * 4 + i][tx * 4 + j] = p;
        ps += p;
      }
#pragma unroll
      for (int o = 8; o > 0; o >>= 1)
        ps += __shfl_xor_sync(0xffffffffu, ps, o);
      l_i[i] = l_i[i] * cf_i[i] + ps;
    }
    if (tx == 0) {
#pragma unroll
      for (int i = 0; i < 4; i++) cfs[ty * 4 + i] = cf_i[i];
    }
    __syncthreads();

    // AV accumulate: thread owns row r, dims dc..dc+7
    float cf = cfs[r];
#pragma unroll
    for (int i = 0; i < 8; i++) O[i] *= cf;
#pragma unroll 4
    for (int j = 0; j < BKT; j++) {
      float p = Ss[r][j];
      float4 v0 = *(const float4*)&Vs[j][dc];
      float4 v1 = *(const float4*)&Vs[j][dc + 4];
      O[0] = fmaf(p, v0.x, O[0]); O[1] = fmaf(p, v0.y, O[1]);
      O[2] = fmaf(p, v0.z, O[2]); O[3] = fmaf(p, v0.w, O[3]);
      O[4] = fmaf(p, v1.x, O[4]); O[5] = fmaf(p, v1.y, O[5]);
      O[6] = fmaf(p, v1.z, O[6]); O[7] = fmaf(p, v1.w, O[7]);
    }
  }

  if (tx == 0) {
#pragma unroll
    for (int i = 0; i < 4; i++) lfin[ty * 4 + i] = l_i[i];
  }
  __syncthreads();
  float inv = 1.0f / lfin[r];
  float* ob = out + (size_t)(b * SEQ + q0 + r) * D_MODEL + h * 32 + dc;
#pragma unroll
  for (int i = 0; i < 8; i++) ob[i] = O[i] * inv;
}

// ---------------------------------------------------------------------------
// Launch
// ---------------------------------------------------------------------------
extern "C" void kernel_launch(void* const* d_in, const int* in_sizes, int n_in,
                              void* d_out, int out_size) {
  const float* x         = (const float*)d_in[0];
  const float* tok_w     = (const float*)d_in[1];
  const float* tok_b     = (const float*)d_in[2];
  const float* tnorm_g   = (const float*)d_in[3];
  const float* tnorm_b   = (const float*)d_in[4];
  const float* in_proj_w = (const float*)d_in[5];
  const float* in_proj_b = (const float*)d_in[6];
  const float* out_w     = (const float*)d_in[7];
  const float* out_b     = (const float*)d_in[8];
  const float* ln1_g     = (const float*)d_in[9];
  const float* ln1_b     = (const float*)d_in[10];
  const float* ln2_g     = (const float*)d_in[11];
  const float* ln2_b     = (const float*)d_in[12];
  const float* lin1_w    = (const float*)d_in[13];
  const float* lin1_b    = (const float*)d_in[14];
  const float* lin2_w    = (const float*)d_in[15];
  const float* lin2_b    = (const float*)d_in[16];
  const float* fnorm_g   = (const float*)d_in[17];
  const float* fnorm_b   = (const float*)d_in[18];
  float* out = (float*)d_out;

  float *y, *h, *qkv, *att, *ff;
  cudaGetSymbolAddress((void**)&y, g_y);
  cudaGetSymbolAddress((void**)&h, g_h);
  cudaGetSymbolAddress((void**)&qkv, g_qkv);
  cudaGetSymbolAddress((void**)&att, g_att);
  cudaGetSymbolAddress((void**)&ff, g_ff);

  const int M = M_ROWS;
  dim3 blk(256);

  gemm_kernel<false, false><<<dim3(D_MODEL / 128, M / 128), blk>>>(
      x, tok_w, tok_b, nullptr, y, M, D_MODEL, T_IN);
  ln_kernel<<<M, blk>>>(y, tnorm_g, tnorm_b, h);

  for (int i = 0; i < N_LAYERS; i++) {
    ln_kernel<<<M, blk>>>(h, ln1_g + i * D_MODEL, ln1_b + i * D_MODEL, y);
    gemm_kernel<false, false><<<dim3(768 / 128, M / 128), blk>>>(
        y, in_proj_w + (size_t)i * 768 * D_MODEL, in_proj_b + i * 768, nullptr,
        qkv, M, 768, D_MODEL);
    rope_kernel<<<(M_ROWS * 128) / 256, blk>>>(qkv);
    attn_kernel<<<dim3(SEQ / BQ, 16 * N_HEADS), blk>>>(qkv, att);
    gemm_kernel<false, true><<<dim3(D_MODEL / 128, M / 128), blk>>>(
        att, out_w + (size_t)i * D_MODEL * D_MODEL, out_b + i * D_MODEL, h, h,
        M, D_MODEL, D_MODEL);
    ln_kernel<<<M, blk>>>(h, ln2_g + i * D_MODEL, ln2_b + i * D_MODEL, y);
    gemm_kernel<true, false><<<dim3(FF_DIM / 128, M / 128), blk>>>(
        y, lin1_w + (size_t)i * FF_DIM * D_MODEL, lin1_b + i * FF_DIM, nullptr,
        ff, M, FF_DIM, D_MODEL);
    gemm_kernel<false, true><<<dim3(D_MODEL / 128, M / 128), blk>>>(
        ff, lin2_w + (size_t)i * D_MODEL * FF_DIM, lin2_b + i * D_MODEL, h, h,
        M, D_MODEL, FF_DIM);
  }

  ln_kernel<<<M, blk>>>(h, fnorm_g, fnorm_b, out);
}

// round 4
// speedup vs baseline: 1.2223x; 1.1348x over previous
#include <cuda_runtime.h>
#include <math.h>

// ---------------------------------------------------------------------------
// iTransformer encoder, round 4: all-fp32 (precision budget is tight),
// BK=16 double-buffered SGEMM + LDS-lean flash attention (transposed probs).
// B=16, S=1024, T=512, D=256, H=8, DH=32, L=4, FF=1024. M = B*S = 16384.
// ---------------------------------------------------------------------------

#define M_ROWS 16384
#define D_MODEL 256
#define T_IN 512
#define FF_DIM 1024
#define N_HEADS 8
#define DH 32
#define SEQ 1024
#define N_LAYERS 4

__device__ float g_y[M_ROWS * D_MODEL];
__device__ float g_h[M_ROWS * D_MODEL];
__device__ float g_qkv[M_ROWS * 3 * D_MODEL];
__device__ float g_att[M_ROWS * D_MODEL];
__device__ float g_ff[M_ROWS * FF_DIM];

// ---------------------------------------------------------------------------
// GEMM: C[M,N] = A[M,K] @ B[N,K]^T + bias[N] (+ReLU) (+residual)
// BM=128, BN=128, BK=16, 256 threads, 8x8 per thread, double-buffered smem.
// Requires M%128==0, N%128==0, K%16==0 (true for all call sites).
// ---------------------------------------------------------------------------
#define GEMM_COMPUTE(BUFIDX)                                                 \
  _Pragma("unroll") for (int kk = 0; kk < 16; kk++) {                        \
    float4 a0 = *(const float4*)&As[BUFIDX][kk][ty * 4];                     \
    float4 a1 = *(const float4*)&As[BUFIDX][kk][ty * 4 + 64];                \
    float4 b0 = *(const float4*)&Bs[BUFIDX][kk][tx * 4];                     \
    float4 b1 = *(const float4*)&Bs[BUFIDX][kk][tx * 4 + 64];                \
    float ra[8] = {a0.x, a0.y, a0.z, a0.w, a1.x, a1.y, a1.z, a1.w};          \
    float rb[8] = {b0.x, b0.y, b0.z, b0.w, b1.x, b1.y, b1.z, b1.w};          \
    _Pragma("unroll") for (int i = 0; i < 8; i++)                            \
        _Pragma("unroll") for (int j = 0; j < 8; j++) acc[i][j] =            \
        fmaf(ra[i], rb[j], acc[i][j]);                                       \
  }

#define GEMM_STAGE(BUF)                                                      \
  do {                                                                       \
    As[BUF][ls + 0][lr] = va0.x; As[BUF][ls + 1][lr] = va0.y;                \
    As[BUF][ls + 2][lr] = va0.z; As[BUF][ls + 3][lr] = va0.w;                \
    As[BUF][ls + 4][lr] = va1.x; As[BUF][ls + 5][lr] = va1.y;                \
    As[BUF][ls + 6][lr] = va1.z; As[BUF][ls + 7][lr] = va1.w;                \
    Bs[BUF][ls + 0][lr] = vb0.x; Bs[BUF][ls + 1][lr] = vb0.y;                \
    Bs[BUF][ls + 2][lr] = vb0.z; Bs[BUF][ls + 3][lr] = vb0.w;                \
    Bs[BUF][ls + 4][lr] = vb1.x; Bs[BUF][ls + 5][lr] = vb1.y;                \
    Bs[BUF][ls + 6][lr] = vb1.z; Bs[BUF][ls + 7][lr] = vb1.w;                \
  } while (0)

template <bool RELU, bool RES>
__global__ __launch_bounds__(256, 2) void gemm_kernel(
    const float* __restrict__ A, const float* __restrict__ B,
    const float* __restrict__ bias, const float* __restrict__ res,
    float* __restrict__ C, int M, int N, int K) {
  __shared__ float As[2][16][132];
  __shared__ float Bs[2][16][132];

  const int tid = threadIdx.x;
  const int tx = tid & 15;
  const int ty = tid >> 4;
  const int m0 = blockIdx.y * 128;
  const int n0 = blockIdx.x * 128;

  const int lr = tid >> 1;         // 0..127
  const int ls = (tid & 1) * 8;    // k offset 0 or 8

  const float* Ap = A + (size_t)(m0 + lr) * K + ls;
  const float* Bp = B + (size_t)(n0 + lr) * K + ls;

  float acc[8][8];
#pragma unroll
  for (int i = 0; i < 8; i++)
#pragma unroll
    for (int j = 0; j < 8; j++) acc[i][j] = 0.f;

  {
    float4 va0 = *(const float4*)(Ap);
    float4 va1 = *(const float4*)(Ap + 4);
    float4 vb0 = *(const float4*)(Bp);
    float4 vb1 = *(const float4*)(Bp + 4);
    GEMM_STAGE(0);
  }
  __syncthreads();

  int buf = 0;
  for (int k0 = 16; k0 < K; k0 += 16) {
    float4 va0 = *(const float4*)(Ap + k0);
    float4 va1 = *(const float4*)(Ap + k0 + 4);
    float4 vb0 = *(const float4*)(Bp + k0);
    float4 vb1 = *(const float4*)(Bp + k0 + 4);
    GEMM_COMPUTE(buf);
    const int nxt = buf ^ 1;
    GEMM_STAGE(nxt);
    __syncthreads();
    buf = nxt;
  }
  GEMM_COMPUTE(buf);

#pragma unroll
  for (int jb = 0; jb < 2; jb++) {
    const int col = n0 + tx * 4 + jb * 64;
    float4 bb = *(const float4*)&bias[col];
#pragma unroll
    for (int i = 0; i < 8; i++) {
      const int row = m0 + ty * 4 + (i & 3) + (i >> 2) * 64;
      float4 r;
      r.x = acc[i][jb * 4 + 0] + bb.x;
      r.y = acc[i][jb * 4 + 1] + bb.y;
      r.z = acc[i][jb * 4 + 2] + bb.z;
      r.w = acc[i][jb * 4 + 3] + bb.w;
      if (RELU) {
        r.x = fmaxf(r.x, 0.f); r.y = fmaxf(r.y, 0.f);
        r.z = fmaxf(r.z, 0.f); r.w = fmaxf(r.w, 0.f);
      }
      if (RES) {
        float4 rr = *(const float4*)&res[(size_t)row * N + col];
        r.x += rr.x; r.y += rr.y; r.z += rr.z; r.w += rr.w;
      }
      *(float4*)&C[(size_t)row * N + col] = r;
    }
  }
}

// ---------------------------------------------------------------------------
// LayerNorm over last dim (256). One block per row.
// ---------------------------------------------------------------------------
__global__ __launch_bounds__(256) void ln_kernel(
    const float* __restrict__ in, const float* __restrict__ g,
    const float* __restrict__ b, float* __restrict__ out) {
  const int row = blockIdx.x;
  const int t = threadIdx.x;
  float v = in[(size_t)row * D_MODEL + t];

  float s = v;
#pragma unroll
  for (int o = 16; o > 0; o >>= 1) s += __shfl_xor_sync(0xffffffffu, s, o);
  __shared__ float ws[8];
  __shared__ float ws2[8];
  if ((t & 31) == 0) ws[t >> 5] = s;
  __syncthreads();
  float mean = (ws[0] + ws[1] + ws[2] + ws[3] + ws[4] + ws[5] + ws[6] + ws[7]) *
               (1.0f / 256.0f);
  float d = v - mean;
  float s2 = d * d;
#pragma unroll
  for (int o = 16; o > 0; o >>= 1) s2 += __shfl_xor_sync(0xffffffffu, s2, o);
  if ((t & 31) == 0) ws2[t >> 5] = s2;
  __syncthreads();
  float var = (ws2[0] + ws2[1] + ws2[2] + ws2[3] + ws2[4] + ws2[5] + ws2[6] +
               ws2[7]) * (1.0f / 256.0f);
  out[(size_t)row * D_MODEL + t] = d * rsqrtf(var + 1e-5f) * g[t] + b[t];
}

// ---------------------------------------------------------------------------
// RoPE in-place on q,k of qkv.
// ---------------------------------------------------------------------------
__global__ __launch_bounds__(256) void rope_kernel(float* __restrict__ qkv) {
  int idx = blockIdx.x * 256 + threadIdx.x;  // M_ROWS * 8 * 16
  int j = idx & 15;
  int h = (idx >> 4) & 7;
  int row = idx >> 7;
  int s = row & (SEQ - 1);
  float inv_freq = 1.0f / powf(10000.0f, (float)j * 0.0625f);
  float freq = (float)s * inv_freq;
  float c, sn;
  sincosf(freq, &c, &sn);
  size_t base = (size_t)row * 768 + h * 32 + j;
  float q1 = qkv[base], q2 = qkv[base + 16];
  qkv[base]      = q1 * c - q2 * sn;
  qkv[base + 16] = q2 * c + q1 * sn;
  float k1 = qkv[base + 256], k2 = qkv[base + 272];
  qkv[base + 256] = k1 * c - k2 * sn;
  qkv[base + 272] = k2 * c + k1 * sn;
}

// ---------------------------------------------------------------------------
// Flash attention, fp32. Grid (S/64, B*H), 256 threads.
// QK: thread (ty,tx) owns score rows ty*4..+3, cols tx*4..+3.
// Probs stored TRANSPOSED Ps[k][q] with XOR-swizzled 16B column groups.
// AV: thread (ty, jh=tx>>3, dm=tx&7) accumulates O[rows ty*4..+3][dims dm*4..+3]
// over its j-half; final cross-half reduce via shfl.xor(8).
// ---------------------------------------------------------------------------
#define BQ 64
#define BKT 64
__global__ __launch_bounds__(256) void attn_kernel(
    const float* __restrict__ qkv, float* __restrict__ out) {
  __shared__ float Qt[DH][BQ];        // [d][q], pre-scaled
  __shared__ float Kt[DH][BKT];       // [d][k]
  __shared__ float Vs[BKT][36];       // [k][d] padded
  __shared__ float Ps[BKT][68];       // [k][q] transposed, swizzled col groups

  const int tid = threadIdx.x;
  const int bh = blockIdx.y;
  const int b = bh >> 3;
  const int h = bh & 7;
  const int q0 = blockIdx.x * BQ;
  const float scale = 0.17677669529663687f;  // 1/sqrt(32)

  // load mappings
  const int lr = tid & 63;        // row (q or k) for transposed Q/K stores
  const int lds = tid >> 6;       // d-slice 0..3 (dims lds*8..+7); conflict-free
  const int r64 = tid >> 2;       // row for V loads
  const int dc = (tid & 3) << 3;  // dim offset for V loads

  // compute mappings
  const int tx = tid & 15;
  const int ty = tid >> 4;
  const int jh = tx >> 3;         // j-half 0/1
  const int dm = tx & 7;          // dim group (4 dims)

  {  // Q tile once (transposed, scaled)
    const float* qb = qkv + (size_t)(b * SEQ + q0 + lr) * 768 + h * 32 + lds * 8;
#pragma unroll
    for (int i = 0; i < 8; i++) Qt[lds * 8 + i][lr] = qb[i] * scale;
  }

  float m_i[4], l_i[4];
#pragma unroll
  for (int i = 0; i < 4; i++) { m_i[i] = -INFINITY; l_i[i] = 0.f; }
  float O[4][4];
#pragma unroll
  for (int i = 0; i < 4; i++)
#pragma unroll
    for (int d = 0; d < 4; d++) O[i][d] = 0.f;

  for (int kt = 0; kt < SEQ / BKT; kt++) {
    const int k0 = kt * BKT;
    __syncthreads();  // previous tile fully consumed
    {
      const float* kb =
          qkv + (size_t)(b * SEQ + k0 + lr) * 768 + 256 + h * 32 + lds * 8;
#pragma unroll
      for (int i = 0; i < 8; i++) Kt[lds * 8 + i][lr] = kb[i];
      const float* vb =
          qkv + (size_t)(b * SEQ + k0 + r64) * 768 + 512 + h * 32 + dc;
      *(float4*)&Vs[r64][dc] = *(const float4*)vb;
      *(float4*)&Vs[r64][dc + 4] = *(const float4*)(vb + 4);
    }
    __syncthreads();

    // ---- QK^T: 4x4 scores per thread ----
    float s4[4][4];
#pragma unroll
    for (int i = 0; i < 4; i++)
#pragma unroll
      for (int j = 0; j < 4; j++) s4[i][j] = 0.f;
#pragma unroll
    for (int d = 0; d < DH; d++) {
      float4 qv = *(const float4*)&Qt[d][ty * 4];
      float4 kv = *(const float4*)&Kt[d][tx * 4];
      float qa[4] = {qv.x, qv.y, qv.z, qv.w};
      float ka[4] = {kv.x, kv.y, kv.z, kv.w};
#pragma unroll
      for (int i = 0; i < 4; i++)
#pragma unroll
        for (int j = 0; j < 4; j++) s4[i][j] = fmaf(qa[i], ka[j], s4[i][j]);
    }

    // ---- online softmax (row reductions over 16 tx lanes) ----
    // store swizzle: column group c' = ty ^ ((k>>3)&7), k = tx*4+j  (=> tx>>1)
    const int swz = (ty ^ (tx >> 1)) * 4;
    float cf_i[4];
#pragma unroll
    for (int i = 0; i < 4; i++) {
      float lm = fmaxf(fmaxf(s4[i][0], s4[i][1]), fmaxf(s4[i][2], s4[i][3]));
#pragma unroll
      for (int o = 8; o > 0; o >>= 1)
        lm = fmaxf(lm, __shfl_xor_sync(0xffffffffu, lm, o));
      float mn = fmaxf(m_i[i], lm);
      cf_i[i] = __expf(m_i[i] - mn);  // 0 on first tile
      m_i[i] = mn;
      float ps = 0.f;
#pragma unroll
      for (int j = 0; j < 4; j++) {
        float p = __expf(s4[i][j] - mn);
        Ps[tx * 4 + j][swz + i] = p;
        ps += p;
      }
#pragma unroll
      for (int o = 8; o > 0; o >>= 1)
        ps += __shfl_xor_sync(0xffffffffu, ps, o);
      l_i[i] = l_i[i] * cf_i[i] + ps;
    }
#pragma unroll
    for (int i = 0; i < 4; i++)
#pragma unroll
      for (int d = 0; d < 4; d++) O[i][d] *= cf_i[i];
    __syncthreads();  // Ps complete

    // ---- AV: O[rows ty*4..+3][dims dm*4..+3] over j in this half ----
#pragma unroll
    for (int jblk = 0; jblk < 4; jblk++) {
      const int c4 = (ty ^ ((jh * 4 + jblk) & 7)) * 4;  // de-swizzled col group
#pragma unroll
      for (int jj = 0; jj < 8; jj++) {
        const int j = jh * 32 + jblk * 8 + jj;
        float4 p4 = *(const float4*)&Ps[j][c4];
        float4 v4 = *(const float4*)&Vs[j][dm * 4];
        float pa[4] = {p4.x, p4.y, p4.z, p4.w};
        float va[4] = {v4.x, v4.y, v4.z, v4.w};
#pragma unroll
        for (int i = 0; i < 4; i++)
#pragma unroll
          for (int d = 0; d < 4; d++)
            O[i][d] = fmaf(pa[i], va[d], O[i][d]);
      }
    }
  }

  // reduce across j-halves (lanes tx and tx^8)
#pragma unroll
  for (int i = 0; i < 4; i++)
#pragma unroll
    for (int d = 0; d < 4; d++)
      O[i][d] += __shfl_xor_sync(0xffffffffu, O[i][d], 8);

  if (jh == 0) {
#pragma unroll
    for (int i = 0; i < 4; i++) {
      const float inv = 1.0f / l_i[i];
      float4 r = make_float4(O[i][0] * inv, O[i][1] * inv, O[i][2] * inv,
                             O[i][3] * inv);
      *(float4*)&out[(size_t)(b * SEQ + q0 + ty * 4 + i) * D_MODEL + h * 32 +
                     dm * 4] = r;
    }
  }
}

// ---------------------------------------------------------------------------
// Launch
// ---------------------------------------------------------------------------
extern "C" void kernel_launch(void* const* d_in, const int* in_sizes, int n_in,
                              void* d_out, int out_size) {
  const float* x         = (const float*)d_in[0];
  const float* tok_w     = (const float*)d_in[1];
  const float* tok_b     = (const float*)d_in[2];
  const float* tnorm_g   = (const float*)d_in[3];
  const float* tnorm_b   = (const float*)d_in[4];
  const float* in_proj_w = (const float*)d_in[5];
  const float* in_proj_b = (const float*)d_in[6];
  const float* out_w     = (const float*)d_in[7];
  const float* out_b     = (const float*)d_in[8];
  const float* ln1_g     = (const float*)d_in[9];
  const float* ln1_b     = (const float*)d_in[10];
  const float* ln2_g     = (const float*)d_in[11];
  const float* ln2_b     = (const float*)d_in[12];
  const float* lin1_w    = (const float*)d_in[13];
  const float* lin1_b    = (const float*)d_in[14];
  const float* lin2_w    = (const float*)d_in[15];
  const float* lin2_b    = (const float*)d_in[16];
  const float* fnorm_g   = (const float*)d_in[17];
  const float* fnorm_b   = (const float*)d_in[18];
  float* out = (float*)d_out;

  float *y, *h, *qkv, *att, *ff;
  cudaGetSymbolAddress((void**)&y, g_y);
  cudaGetSymbolAddress((void**)&h, g_h);
  cudaGetSymbolAddress((void**)&qkv, g_qkv);
  cudaGetSymbolAddress((void**)&att, g_att);
  cudaGetSymbolAddress((void**)&ff, g_ff);

  const int M = M_ROWS;
  dim3 blk(256);

  gemm_kernel<false, false><<<dim3(D_MODEL / 128, M / 128), blk>>>(
      x, tok_w, tok_b, nullptr, y, M, D_MODEL, T_IN);
  ln_kernel<<<M, blk>>>(y, tnorm_g, tnorm_b, h);

  for (int i = 0; i < N_LAYERS; i++) {
    ln_kernel<<<M, blk>>>(h, ln1_g + i * D_MODEL, ln1_b + i * D_MODEL, y);
    gemm_kernel<false, false><<<dim3(768 / 128, M / 128), blk>>>(
        y, in_proj_w + (size_t)i * 768 * D_MODEL, in_proj_b + i * 768, nullptr,
        qkv, M, 768, D_MODEL);
    rope_kernel<<<(M_ROWS * 128) / 256, blk>>>(qkv);
    attn_kernel<<<dim3(SEQ / BQ, 16 * N_HEADS), blk>>>(qkv, att);
    gemm_kernel<false, true><<<dim3(D_MODEL / 128, M / 128), blk>>>(
        att, out_w + (size_t)i * D_MODEL * D_MODEL, out_b + i * D_MODEL, h, h,
        M, D_MODEL, D_MODEL);
    ln_kernel<<<M, blk>>>(h, ln2_g + i * D_MODEL, ln2_b + i * D_MODEL, y);
    gemm_kernel<true, false><<<dim3(FF_DIM / 128, M / 128), blk>>>(
        y, lin1_w + (size_t)i * FF_DIM * D_MODEL, lin1_b + i * FF_DIM, nullptr,
        ff, M, FF_DIM, D_MODEL);
    gemm_kernel<false, true><<<dim3(D_MODEL / 128, M / 128), blk>>>(
        ff, lin2_w + (size_t)i * D_MODEL * FF_DIM, lin2_b + i * D_MODEL, h, h,
        M, D_MODEL, FF_DIM);
  }

  ln_kernel<<<M, blk>>>(h, fnorm_g, fnorm_b, out);
}

// round 5
// speedup vs baseline: 1.2574x; 1.0287x over previous
#include <cuda_runtime.h>
#include <math.h>
#include <stdint.h>

// ---------------------------------------------------------------------------
// iTransformer encoder, round 5: 3xTF32 tensor-core GEMMs (fp32-accurate) +
// fp32 flash attention (R4 version).
// B=16, S=1024, T=512, D=256, H=8, DH=32, L=4, FF=1024. M = B*S = 16384.
// ---------------------------------------------------------------------------

#define M_ROWS 16384
#define D_MODEL 256
#define T_IN 512
#define FF_DIM 1024
#define N_HEADS 8
#define DH 32
#define SEQ 1024
#define N_LAYERS 4

__device__ float g_y[M_ROWS * D_MODEL];
__device__ float g_h[M_ROWS * D_MODEL];
__device__ float g_qkv[M_ROWS * 3 * D_MODEL];
__device__ float g_att[M_ROWS * D_MODEL];
__device__ float g_ff[M_ROWS * FF_DIM];

__device__ __forceinline__ float tf32_round(float x) {
  uint32_t u;
  asm("cvt.rna.tf32.f32 %0, %1;" : "=r"(u) : "f"(x));
  return __uint_as_float(u);
}

__device__ __forceinline__ void mma_tf32(float* d, const uint32_t* a,
                                         const uint32_t* b) {
  asm volatile(
      "mma.sync.aligned.m16n8k8.row.col.f32.tf32.tf32.f32 "
      "{%0,%1,%2,%3}, {%4,%5,%6,%7}, {%8,%9}, {%0,%1,%2,%3};\n"
      : "+f"(d[0]), "+f"(d[1]), "+f"(d[2]), "+f"(d[3])
      : "r"(a[0]), "r"(a[1]), "r"(a[2]), "r"(a[3]), "r"(b[0]), "r"(b[1]));
}

// ---------------------------------------------------------------------------
// 3xTF32 GEMM: C[M,N] = A[M,K] @ B[N,K]^T + bias[N] (+ReLU) (+residual)
// Block 128x128xK16, 8 warps (2x4), warp tile 64x32, mma m16n8k8.
// Each fp32 x is split hi=tf32(x), lo=tf32(x-hi); D += AhiBhi + AhiBlo + AloBhi.
// smem: float4 per (row, c): (hi(k=c), hi(k=c+4), lo(k=c), lo(k=c+4)),
// c-index XOR-permuted by (row&3)^(slice<<1) -> conflict-free LDS/STS.
// Dynamic smem 64KB, double-buffered. Requires M%128==0, N%128==0, K%16==0.
// ---------------------------------------------------------------------------
#define AS(buf, s, row, c) AsP[((((buf)*2 + (s)) * 128 + (row)) << 2) + (c)]
#define BS(buf, s, row, c) BsP[((((buf)*2 + (s)) * 128 + (row)) << 2) + (c)]
#define GEMM_SMEM_BYTES (2 * 2 * 128 * 4 * 16 * 2)

#define STAGE_STORE(BUF)                                                       \
  do {                                                                         \
    float ah[8], al[8], bh[8], bl[8];                                          \
    ah[0] = tf32_round(va0.x); ah[1] = tf32_round(va0.y);                      \
    ah[2] = tf32_round(va0.z); ah[3] = tf32_round(va0.w);                      \
    ah[4] = tf32_round(va1.x); ah[5] = tf32_round(va1.y);                      \
    ah[6] = tf32_round(va1.z); ah[7] = tf32_round(va1.w);                      \
    al[0] = tf32_round(va0.x - ah[0]); al[1] = tf32_round(va0.y - ah[1]);      \
    al[2] = tf32_round(va0.z - ah[2]); al[3] = tf32_round(va0.w - ah[3]);      \
    al[4] = tf32_round(va1.x - ah[4]); al[5] = tf32_round(va1.y - ah[5]);      \
    al[6] = tf32_round(va1.z - ah[6]); al[7] = tf32_round(va1.w - ah[7]);      \
    bh[0] = tf32_round(vb0.x); bh[1] = tf32_round(vb0.y);                      \
    bh[2] = tf32_round(vb0.z); bh[3] = tf32_round(vb0.w);                      \
    bh[4] = tf32_round(vb1.x); bh[5] = tf32_round(vb1.y);                      \
    bh[6] = tf32_round(vb1.z); bh[7] = tf32_round(vb1.w);                      \
    bl[0] = tf32_round(vb0.x - bh[0]); bl[1] = tf32_round(vb0.y - bh[1]);      \
    bl[2] = tf32_round(vb0.z - bh[2]); bl[3] = tf32_round(vb0.w - bh[3]);      \
    bl[4] = tf32_round(vb1.x - bh[4]); bl[5] = tf32_round(vb1.y - bh[5]);      \
    bl[6] = tf32_round(vb1.z - bh[6]); bl[7] = tf32_round(vb1.w - bh[7]);      \
    const int prm = (lrow & 3) ^ (lsl << 1);                                   \
    _Pragma("unroll") for (int c = 0; c < 4; c++) {                            \
      AS(BUF, lsl, lrow, c ^ prm) =                                            \
          make_float4(ah[c], ah[c + 4], al[c], al[c + 4]);                     \
      BS(BUF, lsl, lrow, c ^ prm) =                                            \
          make_float4(bh[c], bh[c + 4], bl[c], bl[c + 4]);                     \
    }                                                                          \
  } while (0)

#define COMPUTE_STAGE(BUF)                                                     \
  _Pragma("unroll") for (int s = 0; s < 2; s++) {                              \
    uint32_t bfH[4][2], bfL[4][2];                                             \
    _Pragma("unroll") for (int nt = 0; nt < 4; nt++) {                         \
      const int row = wn * 32 + nt * 8 + gid;                                  \
      float4 pb = BS(BUF, s, row, tg ^ (row & 3) ^ (s << 1));                  \
      bfH[nt][0] = __float_as_uint(pb.x); bfH[nt][1] = __float_as_uint(pb.y);  \
      bfL[nt][0] = __float_as_uint(pb.z); bfL[nt][1] = __float_as_uint(pb.w);  \
    }                                                                          \
    _Pragma("unroll") for (int mt = 0; mt < 4; mt++) {                         \
      const int rb = wm * 64 + mt * 16 + gid;                                  \
      const int pc = tg ^ (rb & 3) ^ (s << 1);                                 \
      float4 p0 = AS(BUF, s, rb, pc);                                          \
      float4 p8 = AS(BUF, s, rb + 8, pc);                                      \
      uint32_t afH[4] = {__float_as_uint(p0.x), __float_as_uint(p8.x),         \
                         __float_as_uint(p0.y), __float_as_uint(p8.y)};        \
      uint32_t afL[4] = {__float_as_uint(p0.z), __float_as_uint(p8.z),         \
                         __float_as_uint(p0.w), __float_as_uint(p8.w)};        \
      _Pragma("unroll") for (int nt = 0; nt < 4; nt++) {                       \
        mma_tf32(acc[mt][nt], afH, bfH[nt]);                                   \
        mma_tf32(acc[mt][nt], afH, bfL[nt]);                                   \
        mma_tf32(acc[mt][nt], afL, bfH[nt]);                                   \
      }                                                                        \
    }                                                                          \
  }

template <bool RELU, bool RES>
__global__ __launch_bounds__(256, 2) void gemm_tf32x3_kernel(
    const float* __restrict__ A, const float* __restrict__ B,
    const float* __restrict__ bias, const float* __restrict__ res,
    float* __restrict__ C, int M, int N, int K) {
  extern __shared__ float4 smem_dyn[];
  float4* AsP = smem_dyn;
  float4* BsP = smem_dyn + 2 * 2 * 128 * 4;

  const int tid = threadIdx.x;
  const int lane = tid & 31;
  const int warp = tid >> 5;
  const int wm = warp >> 2;
  const int wn = warp & 3;
  const int gid = lane >> 2;
  const int tg = lane & 3;

  const int m0 = blockIdx.y * 128;
  const int n0 = blockIdx.x * 128;

  const int lrow = tid >> 1;     // 0..127
  const int lsl = tid & 1;       // k-slice 0/1

  const float* Ap = A + (size_t)(m0 + lrow) * K + lsl * 8;
  const float* Bp = B + (size_t)(n0 + lrow) * K + lsl * 8;

  float acc[4][4][4];
#pragma unroll
  for (int i = 0; i < 4; i++)
#pragma unroll
    for (int j = 0; j < 4; j++)
#pragma unroll
      for (int r = 0; r < 4; r++) acc[i][j][r] = 0.f;

  {
    float4 va0 = *(const float4*)(Ap);
    float4 va1 = *(const float4*)(Ap + 4);
    float4 vb0 = *(const float4*)(Bp);
    float4 vb1 = *(const float4*)(Bp + 4);
    STAGE_STORE(0);
  }
  __syncthreads();

  int buf = 0;
  for (int k0 = 16; k0 < K; k0 += 16) {
    float4 va0 = *(const float4*)(Ap + k0);
    float4 va1 = *(const float4*)(Ap + k0 + 4);
    float4 vb0 = *(const float4*)(Bp + k0);
    float4 vb1 = *(const float4*)(Bp + k0 + 4);
    COMPUTE_STAGE(buf);
    const int nxt = buf ^ 1;
    STAGE_STORE(nxt);
    __syncthreads();
    buf = nxt;
  }
  COMPUTE_STAGE(buf);

#pragma unroll
  for (int mt = 0; mt < 4; mt++) {
    const int row = m0 + wm * 64 + mt * 16 + gid;
#pragma unroll
    for (int nt = 0; nt < 4; nt++) {
      const int col = n0 + wn * 32 + nt * 8 + tg * 2;
      float2 bb = *(const float2*)&bias[col];
      float2 r0 = make_float2(acc[mt][nt][0] + bb.x, acc[mt][nt][1] + bb.y);
      float2 r1 = make_float2(acc[mt][nt][2] + bb.x, acc[mt][nt][3] + bb.y);
      if (RELU) {
        r0.x = fmaxf(r0.x, 0.f); r0.y = fmaxf(r0.y, 0.f);
        r1.x = fmaxf(r1.x, 0.f); r1.y = fmaxf(r1.y, 0.f);
      }
      if (RES) {
        float2 q0 = *(const float2*)&res[(size_t)row * N + col];
        float2 q1 = *(const float2*)&res[(size_t)(row + 8) * N + col];
        r0.x += q0.x; r0.y += q0.y;
        r1.x += q1.x; r1.y += q1.y;
      }
      *(float2*)&C[(size_t)row * N + col] = r0;
      *(float2*)&C[(size_t)(row + 8) * N + col] = r1;
    }
  }
}

// ---------------------------------------------------------------------------
// LayerNorm over last dim (256). One block per row.
// ---------------------------------------------------------------------------
__global__ __launch_bounds__(256) void ln_kernel(
    const float* __restrict__ in, const float* __restrict__ g,
    const float* __restrict__ b, float* __restrict__ out) {
  const int row = blockIdx.x;
  const int t = threadIdx.x;
  float v = in[(size_t)row * D_MODEL + t];

  float s = v;
#pragma unroll
  for (int o = 16; o > 0; o >>= 1) s += __shfl_xor_sync(0xffffffffu, s, o);
  __shared__ float ws[8];
  __shared__ float ws2[8];
  if ((t & 31) == 0) ws[t >> 5] = s;
  __syncthreads();
  float mean = (ws[0] + ws[1] + ws[2] + ws[3] + ws[4] + ws[5] + ws[6] + ws[7]) *
               (1.0f / 256.0f);
  float d = v - mean;
  float s2 = d * d;
#pragma unroll
  for (int o = 16; o > 0; o >>= 1) s2 += __shfl_xor_sync(0xffffffffu, s2, o);
  if ((t & 31) == 0) ws2[t >> 5] = s2;
  __syncthreads();
  float var = (ws2[0] + ws2[1] + ws2[2] + ws2[3] + ws2[4] + ws2[5] + ws2[6] +
               ws2[7]) * (1.0f / 256.0f);
  out[(size_t)row * D_MODEL + t] = d * rsqrtf(var + 1e-5f) * g[t] + b[t];
}

// ---------------------------------------------------------------------------
// RoPE in-place on q,k of qkv.
// ---------------------------------------------------------------------------
__global__ __launch_bounds__(256) void rope_kernel(float* __restrict__ qkv) {
  int idx = blockIdx.x * 256 + threadIdx.x;  // M_ROWS * 8 * 16
  int j = idx & 15;
  int h = (idx >> 4) & 7;
  int row = idx >> 7;
  int s = row & (SEQ - 1);
  float inv_freq = 1.0f / powf(10000.0f, (float)j * 0.0625f);
  float freq = (float)s * inv_freq;
  float c, sn;
  sincosf(freq, &c, &sn);
  size_t base = (size_t)row * 768 + h * 32 + j;
  float q1 = qkv[base], q2 = qkv[base + 16];
  qkv[base]      = q1 * c - q2 * sn;
  qkv[base + 16] = q2 * c + q1 * sn;
  float k1 = qkv[base + 256], k2 = qkv[base + 272];
  qkv[base + 256] = k1 * c - k2 * sn;
  qkv[base + 272] = k2 * c + k1 * sn;
}

// ---------------------------------------------------------------------------
// Flash attention, fp32 (R4 version). Grid (S/64, B*H), 256 threads.
// ---------------------------------------------------------------------------
#define BQ 64
#define BKT 64
__global__ __launch_bounds__(256) void attn_kernel(
    const float* __restrict__ qkv, float* __restrict__ out) {
  __shared__ float Qt[DH][BQ];
  __shared__ float Kt[DH][BKT];
  __shared__ float Vs[BKT][36];
  __shared__ float Ps[BKT][68];

  const int tid = threadIdx.x;
  const int bh = blockIdx.y;
  const int b = bh >> 3;
  const int h = bh & 7;
  const int q0 = blockIdx.x * BQ;
  const float scale = 0.17677669529663687f;

  const int lr = tid & 63;
  const int lds = tid >> 6;
  const int r64 = tid >> 2;
  const int dc = (tid & 3) << 3;

  const int tx = tid & 15;
  const int ty = tid >> 4;
  const int jh = tx >> 3;
  const int dm = tx & 7;

  {
    const float* qb = qkv + (size_t)(b * SEQ + q0 + lr) * 768 + h * 32 + lds * 8;
#pragma unroll
    for (int i = 0; i < 8; i++) Qt[lds * 8 + i][lr] = qb[i] * scale;
  }

  float m_i[4], l_i[4];
#pragma unroll
  for (int i = 0; i < 4; i++) { m_i[i] = -INFINITY; l_i[i] = 0.f; }
  float O[4][4];
#pragma unroll
  for (int i = 0; i < 4; i++)
#pragma unroll
    for (int d = 0; d < 4; d++) O[i][d] = 0.f;

  for (int kt = 0; kt < SEQ / BKT; kt++) {
    const int k0 = kt * BKT;
    __syncthreads();
    {
      const float* kb =
          qkv + (size_t)(b * SEQ + k0 + lr) * 768 + 256 + h * 32 + lds * 8;
#pragma unroll
      for (int i = 0; i < 8; i++) Kt[lds * 8 + i][lr] = kb[i];
      const float* vb =
          qkv + (size_t)(b * SEQ + k0 + r64) * 768 + 512 + h * 32 + dc;
      *(float4*)&Vs[r64][dc] = *(const float4*)vb;
      *(float4*)&Vs[r64][dc + 4] = *(const float4*)(vb + 4);
    }
    __syncthreads();

    float s4[4][4];
#pragma unroll
    for (int i = 0; i < 4; i++)
#pragma unroll
      for (int j = 0; j < 4; j++) s4[i][j] = 0.f;
#pragma unroll
    for (int d = 0; d < DH; d++) {
      float4 qv = *(const float4*)&Qt[d][ty * 4];
      float4 kv = *(const float4*)&Kt[d][tx * 4];
      float qa[4] = {qv.x, qv.y, qv.z, qv.w};
      float ka[4] = {kv.x, kv.y, kv.z, kv.w};
#pragma unroll
      for (int i = 0; i < 4; i++)
#pragma unroll
        for (int j = 0; j < 4; j++) s4[i][j] = fmaf(qa[i], ka[j], s4[i][j]);
    }

    const int swz = (ty ^ (tx >> 1)) * 4;
    float cf_i[4];
#pragma unroll
    for (int i = 0; i < 4; i++) {
      float lm = fmaxf(fmaxf(s4[i][0], s4[i][1]), fmaxf(s4[i][2], s4[i][3]));
#pragma unroll
      for (int o = 8; o > 0; o >>= 1)
        lm = fmaxf(lm, __shfl_xor_sync(0xffffffffu, lm, o));
      float mn = fmaxf(m_i[i], lm);
      cf_i[i] = __expf(m_i[i] - mn);
      m_i[i] = mn;
      float ps = 0.f;
#pragma unroll
      for (int j = 0; j < 4; j++) {
        float p = __expf(s4[i][j] - mn);
        Ps[tx * 4 + j][swz + i] = p;
        ps += p;
      }
#pragma unroll
      for (int o = 8; o > 0; o >>= 1)
        ps += __shfl_xor_sync(0xffffffffu, ps, o);
      l_i[i] = l_i[i] * cf_i[i] + ps;
    }
#pragma unroll
    for (int i = 0; i < 4; i++)
#pragma unroll
      for (int d = 0; d < 4; d++) O[i][d] *= cf_i[i];
    __syncthreads();

#pragma unroll
    for (int jblk = 0; jblk < 4; jblk++) {
      const int c4 = (ty ^ ((jh * 4 + jblk) & 7)) * 4;
#pragma unroll
      for (int jj = 0; jj < 8; jj++) {
        const int j = jh * 32 + jblk * 8 + jj;
        float4 p4 = *(const float4*)&Ps[j][c4];
        float4 v4 = *(const float4*)&Vs[j][dm * 4];
        float pa[4] = {p4.x, p4.y, p4.z, p4.w};
        float va[4] = {v4.x, v4.y, v4.z, v4.w};
#pragma unroll
        for (int i = 0; i < 4; i++)
#pragma unroll
          for (int d = 0; d < 4; d++)
            O[i][d] = fmaf(pa[i], va[d], O[i][d]);
      }
    }
  }

#pragma unroll
  for (int i = 0; i < 4; i++)
#pragma unroll
    for (int d = 0; d < 4; d++)
      O[i][d] += __shfl_xor_sync(0xffffffffu, O[i][d], 8);

  if (jh == 0) {
#pragma unroll
    for (int i = 0; i < 4; i++) {
      const float inv = 1.0f / l_i[i];
      float4 r = make_float4(O[i][0] * inv, O[i][1] * inv, O[i][2] * inv,
                             O[i][3] * inv);
      *(float4*)&out[(size_t)(b * SEQ + q0 + ty * 4 + i) * D_MODEL + h * 32 +
                     dm * 4] = r;
    }
  }
}

// ---------------------------------------------------------------------------
// Launch
// ---------------------------------------------------------------------------
extern "C" void kernel_launch(void* const* d_in, const int* in_sizes, int n_in,
                              void* d_out, int out_size) {
  const float* x         = (const float*)d_in[0];
  const float* tok_w     = (const float*)d_in[1];
  const float* tok_b     = (const float*)d_in[2];
  const float* tnorm_g   = (const float*)d_in[3];
  const float* tnorm_b   = (const float*)d_in[4];
  const float* in_proj_w = (const float*)d_in[5];
  const float* in_proj_b = (const float*)d_in[6];
  const float* out_w     = (const float*)d_in[7];
  const float* out_b     = (const float*)d_in[8];
  const float* ln1_g     = (const float*)d_in[9];
  const float* ln1_b     = (const float*)d_in[10];
  const float* ln2_g     = (const float*)d_in[11];
  const float* ln2_b     = (const float*)d_in[12];
  const float* lin1_w    = (const float*)d_in[13];
  const float* lin1_b    = (const float*)d_in[14];
  const float* lin2_w    = (const float*)d_in[15];
  const float* lin2_b    = (const float*)d_in[16];
  const float* fnorm_g   = (const float*)d_in[17];
  const float* fnorm_b   = (const float*)d_in[18];
  float* out = (float*)d_out;

  float *y, *h, *qkv, *att, *ff;
  cudaGetSymbolAddress((void**)&y, g_y);
  cudaGetSymbolAddress((void**)&h, g_h);
  cudaGetSymbolAddress((void**)&qkv, g_qkv);
  cudaGetSymbolAddress((void**)&att, g_att);
  cudaGetSymbolAddress((void**)&ff, g_ff);

  const int M = M_ROWS;
  const int SB = GEMM_SMEM_BYTES;
  // idempotent; errors (e.g. if repeated during capture) are harmless
  cudaFuncSetAttribute(gemm_tf32x3_kernel<false, false>,
                       cudaFuncAttributeMaxDynamicSharedMemorySize, SB);
  cudaFuncSetAttribute(gemm_tf32x3_kernel<false, true>,
                       cudaFuncAttributeMaxDynamicSharedMemorySize, SB);
  cudaFuncSetAttribute(gemm_tf32x3_kernel<true, false>,
                       cudaFuncAttributeMaxDynamicSharedMemorySize, SB);

  dim3 blk(256);

  gemm_tf32x3_kernel<false, false><<<dim3(D_MODEL / 128, M / 128), blk, SB>>>(
      x, tok_w, tok_b, nullptr, y, M, D_MODEL, T_IN);
  ln_kernel<<<M, blk>>>(y, tnorm_g, tnorm_b, h);

  for (int i = 0; i < N_LAYERS; i++) {
    ln_kernel<<<M, blk>>>(h, ln1_g + i * D_MODEL, ln1_b + i * D_MODEL, y);
    gemm_tf32x3_kernel<false, false><<<dim3(768 / 128, M / 128), blk, SB>>>(
        y, in_proj_w + (size_t)i * 768 * D_MODEL, in_proj_b + i * 768, nullptr,
        qkv, M, 768, D_MODEL);
    rope_kernel<<<(M_ROWS * 128) / 256, blk>>>(qkv);
    attn_kernel<<<dim3(SEQ / BQ, 16 * N_HEADS), blk>>>(qkv, att);
    gemm_tf32x3_kernel<false, true><<<dim3(D_MODEL / 128, M / 128), blk, SB>>>(
        att, out_w + (size_t)i * D_MODEL * D_MODEL, out_b + i * D_MODEL, h, h,
        M, D_MODEL, D_MODEL);
    ln_kernel<<<M, blk>>>(h, ln2_g + i * D_MODEL, ln2_b + i * D_MODEL, y);
    gemm_tf32x3_kernel<true, false><<<dim3(FF_DIM / 128, M / 128), blk, SB>>>(
        y, lin1_w + (size_t)i * FF_DIM * D_MODEL, lin1_b + i * FF_DIM, nullptr,
        ff, M, FF_DIM, D_MODEL);
    gemm_tf32x3_kernel<false, true><<<dim3(D_MODEL / 128, M / 128), blk, SB>>>(
        ff, lin2_w + (size_t)i * D_MODEL * FF_DIM, lin2_b + i * D_MODEL, h, h,
        M, D_MODEL, FF_DIM);
  }

  ln_kernel<<<M, blk>>>(h, fnorm_g, fnorm_b, out);
}